// round 1
// baseline (speedup 1.0000x reference)
#include <cuda_runtime.h>
#include <math.h>

#define DT 0.01f

static const int T_STEPS = 8388608;
static const int SEG_L   = 64;                     // actions per thread
static const int TPB     = 256;                    // threads per block
static const int NBLK    = T_STEPS / (SEG_L * TPB); // 512
static const int NTHR    = NBLK * TPB;             // 131072

// Scratch (no allocations allowed): per-thread and per-block affine carries.
// Tuple layout: (A, P, X, V) meaning  v_out = A*v_in + V ;  x_out = x_in + P*v_in + X
__device__ float4 g_thr[NTHR];
__device__ float4 g_blk[NBLK];

// Compose: apply f first, then g.
__device__ __forceinline__ float4 comp(float4 f, float4 g) {
    float4 r;
    r.x = g.x * f.x;              // A  = A2*A1
    r.y = f.y + g.y * f.x;        // P  = P1 + P2*A1
    r.z = f.z + g.y * f.w + g.z;  // X  = X1 + P2*V1 + X2
    r.w = g.x * f.w + g.w;        // V  = A2*V1 + V2
    return r;
}

__device__ __forceinline__ void get_coeffs(const float* mass, const float* fric,
                                           float& alpha, float& beta) {
    float m_safe = fabsf(mass[0]) + 0.001f;
    beta  = DT / m_safe;
    alpha = 1.0f - fric[0] * beta;
}

// Pass 1: per-thread segment tuples + block-level exclusive scan.
__global__ void __launch_bounds__(TPB)
k_partial(const float* __restrict__ act,
          const float* __restrict__ mass,
          const float* __restrict__ fric) {
    __shared__ float4 sh[TPB];
    int tid = threadIdx.x;
    int g   = blockIdx.x * TPB + tid;

    float alpha, beta;
    get_coeffs(mass, fric, alpha, beta);

    // Data-dependent part: run recurrence with zero initial state.
    const float4* a4 = reinterpret_cast<const float4*>(act) + g * (SEG_L / 4);
    float v = 0.0f, x = 0.0f;
    #pragma unroll
    for (int j = 0; j < SEG_L / 4; j++) {
        float4 a = a4[j];
        v = alpha * v + beta * a.x; x += DT * v;
        v = alpha * v + beta * a.y; x += DT * v;
        v = alpha * v + beta * a.z; x += DT * v;
        v = alpha * v + beta * a.w; x += DT * v;
    }

    // Homogeneous part in closed form: A = alpha^L, P = DT*alpha*(1-A)/(1-alpha)
    float A = alpha;
    #pragma unroll
    for (int j = 0; j < 6; j++) A *= A;   // alpha^64
    float denom = 1.0f - alpha;
    float P = (denom != 0.0f) ? (DT * alpha * (1.0f - A) / denom)
                              : (DT * (float)SEG_L);

    float4 val = make_float4(A, P, x, v);
    sh[tid] = val;
    __syncthreads();

    // Inclusive Hillis-Steele scan with non-commutative compose.
    for (int d = 1; d < TPB; d <<= 1) {
        float4 left;
        if (tid >= d) left = sh[tid - d];
        __syncthreads();
        if (tid >= d) { val = comp(left, val); sh[tid] = val; }
        __syncthreads();
    }

    // Exclusive within-block prefix for this thread; block total from last thread.
    float4 excl = (tid == 0) ? make_float4(1.0f, 0.0f, 0.0f, 0.0f) : sh[tid - 1];
    g_thr[g] = excl;
    if (tid == TPB - 1) g_blk[blockIdx.x] = val;
}

// Pass 2: exclusive scan over the 512 block totals (single block).
__global__ void __launch_bounds__(NBLK)
k_blockscan() {
    __shared__ float4 sh[NBLK];
    int tid = threadIdx.x;
    float4 val = g_blk[tid];
    sh[tid] = val;
    __syncthreads();
    for (int d = 1; d < NBLK; d <<= 1) {
        float4 left;
        if (tid >= d) left = sh[tid - d];
        __syncthreads();
        if (tid >= d) { val = comp(left, val); sh[tid] = val; }
        __syncthreads();
    }
    g_blk[tid] = (tid == 0) ? make_float4(1.0f, 0.0f, 0.0f, 0.0f) : sh[tid - 1];
}

// Pass 3: apply exclusive prefix to initial state, replay segment, write trajectory.
__global__ void __launch_bounds__(TPB)
k_final(const float* __restrict__ act,
        const float* __restrict__ init,
        const float* __restrict__ mass,
        const float* __restrict__ fric,
        float2* __restrict__ out2) {
    int tid = threadIdx.x;
    int g   = blockIdx.x * TPB + tid;

    float alpha, beta;
    get_coeffs(mass, fric, alpha, beta);

    float x0 = init[0];
    float v0 = init[1];

    // Total exclusive prefix = (all earlier blocks) then (earlier threads in block).
    float4 e = comp(g_blk[blockIdx.x], g_thr[g]);
    float v = e.x * v0 + e.w;
    float x = x0 + e.y * v0 + e.z;

    if (g == 0) out2[0] = make_float2(x0, v0);   // row 0 = initial state

    const float4* a4 = reinterpret_cast<const float4*>(act) + g * (SEG_L / 4);
    float2* o = out2 + 1 + g * SEG_L;
    #pragma unroll
    for (int j = 0; j < SEG_L / 4; j++) {
        float4 a = a4[j];
        v = alpha * v + beta * a.x; x += DT * v; o[4 * j + 0] = make_float2(x, v);
        v = alpha * v + beta * a.y; x += DT * v; o[4 * j + 1] = make_float2(x, v);
        v = alpha * v + beta * a.z; x += DT * v; o[4 * j + 2] = make_float2(x, v);
        v = alpha * v + beta * a.w; x += DT * v; o[4 * j + 3] = make_float2(x, v);
    }
}

extern "C" void kernel_launch(void* const* d_in, const int* in_sizes, int n_in,
                              void* d_out, int out_size) {
    // metadata order: initial_state(2), actions(T), mass(1), friction_coeff(1)
    const float* init = (const float*)d_in[0];
    const float* act  = (const float*)d_in[1];
    const float* mass = (const float*)d_in[2];
    const float* fric = (const float*)d_in[3];
    float2* out2 = (float2*)d_out;

    k_partial<<<NBLK, TPB>>>(act, mass, fric);
    k_blockscan<<<1, NBLK>>>();
    k_final<<<NBLK, TPB>>>(act, init, mass, fric, out2);
}

// round 2
// speedup vs baseline: 2.0962x; 2.0962x over previous
#include <cuda_runtime.h>
#include <math.h>

#define DT 0.01f

#define SEG   32                       // actions per thread
#define TPB   256                      // threads per block
#define NBLK  1024                     // 8388608 / (32*256)
#define TILE  (TPB * SEG)              // 8192 floats per block tile
#define SSTR  36                       // smem stride (floats) per segment: conflict-free LDS.128
#define NTHR  (NBLK * TPB)

// Scratch (no allocation allowed). Tuple (A,P,X,V): v' = A*v + V ; x' = x + P*v + X
__device__ float4 g_thr[NTHR];
__device__ float4 g_blk[NBLK];

__device__ __forceinline__ float4 comp(float4 f, float4 g) {
    float4 r;
    r.x = g.x * f.x;
    r.y = f.y + g.y * f.x;
    r.z = f.z + g.y * f.w + g.z;
    r.w = g.x * f.w + g.w;
    return r;
}

__device__ __forceinline__ void get_coeffs(const float* mass, const float* fric,
                                           float& alpha, float& beta) {
    float m_safe = fabsf(mass[0]) + 0.001f;
    beta  = DT / m_safe;
    alpha = 1.0f - fric[0] * beta;
}

// Coalesced tile load: global float4 -> padded smem (seg-major).
__device__ __forceinline__ void load_tile(const float* __restrict__ act, float* s, int tid, int blk) {
    const float4* g4 = reinterpret_cast<const float4*>(act) + blk * (TILE / 4);
    #pragma unroll
    for (int r = 0; r < TILE / 4 / TPB; r++) {          // 8 iterations
        int i4 = tid + TPB * r;
        float4 v = g4[i4];
        *reinterpret_cast<float4*>(&s[(i4 >> 3) * SSTR + (i4 & 7) * 4]) = v;
    }
}

// ---------------- Pass 1: segment tuples + block scan ----------------
__global__ void __launch_bounds__(TPB)
k_partial(const float* __restrict__ act,
          const float* __restrict__ mass,
          const float* __restrict__ fric) {
    extern __shared__ float s[];                        // [TPB*SSTR] input + scan area
    float4* sh = reinterpret_cast<float4*>(s + TPB * SSTR);
    int tid = threadIdx.x;
    int g   = blockIdx.x * TPB + tid;

    load_tile(act, s, tid, blockIdx.x);
    __syncthreads();

    float alpha, beta;
    get_coeffs(mass, fric, alpha, beta);

    const float* my = s + tid * SSTR;
    float v = 0.0f, x = 0.0f;
    #pragma unroll
    for (int j = 0; j < SEG / 4; j++) {
        float4 a = *reinterpret_cast<const float4*>(my + 4 * j);
        v = alpha * v + beta * a.x; x += DT * v;
        v = alpha * v + beta * a.y; x += DT * v;
        v = alpha * v + beta * a.z; x += DT * v;
        v = alpha * v + beta * a.w; x += DT * v;
    }

    float A = alpha;
    #pragma unroll
    for (int j = 0; j < 5; j++) A *= A;                 // alpha^32
    float denom = 1.0f - alpha;
    float P = (denom != 0.0f) ? (DT * alpha * (1.0f - A) / denom)
                              : (DT * (float)SEG);

    float4 val = make_float4(A, P, x, v);
    sh[tid] = val;
    __syncthreads();
    for (int d = 1; d < TPB; d <<= 1) {
        float4 left;
        if (tid >= d) left = sh[tid - d];
        __syncthreads();
        if (tid >= d) { val = comp(left, val); sh[tid] = val; }
        __syncthreads();
    }
    g_thr[g] = (tid == 0) ? make_float4(1.0f, 0.0f, 0.0f, 0.0f) : sh[tid - 1];
    if (tid == TPB - 1) g_blk[blockIdx.x] = val;
}

// ---------------- Pass 2: exclusive scan of 1024 block totals ----------------
__global__ void __launch_bounds__(NBLK)
k_blockscan() {
    __shared__ float4 sh[NBLK];
    int tid = threadIdx.x;
    float4 val = g_blk[tid];
    sh[tid] = val;
    __syncthreads();
    for (int d = 1; d < NBLK; d <<= 1) {
        float4 left;
        if (tid >= d) left = sh[tid - d];
        __syncthreads();
        if (tid >= d) { val = comp(left, val); sh[tid] = val; }
        __syncthreads();
    }
    g_blk[tid] = (tid == 0) ? make_float4(1.0f, 0.0f, 0.0f, 0.0f) : sh[tid - 1];
}

// ---------------- Pass 3: replay + coalesced trajectory write ----------------
__global__ void __launch_bounds__(TPB)
k_final(const float* __restrict__ act,
        const float* __restrict__ init,
        const float* __restrict__ mass,
        const float* __restrict__ fric,
        float2* __restrict__ out2) {
    extern __shared__ float s[];                        // input tile [TPB*SSTR]
    float2* sout = reinterpret_cast<float2*>(s + TPB * SSTR);  // [128*33] float2
    int tid = threadIdx.x;
    int g   = blockIdx.x * TPB + tid;

    load_tile(act, s, tid, blockIdx.x);
    __syncthreads();

    float alpha, beta;
    get_coeffs(mass, fric, alpha, beta);
    float x0 = init[0];
    float v0 = init[1];

    float4 e = comp(g_blk[blockIdx.x], g_thr[g]);
    float v = e.x * v0 + e.w;
    float x = x0 + e.y * v0 + e.z;

    if (g == 0) out2[0] = make_float2(x0, v0);

    float2 r[SEG];
    const float* my = s + tid * SSTR;
    #pragma unroll
    for (int j = 0; j < SEG / 4; j++) {
        float4 a = *reinterpret_cast<const float4*>(my + 4 * j);
        v = alpha * v + beta * a.x; x += DT * v; r[4 * j + 0] = make_float2(x, v);
        v = alpha * v + beta * a.y; x += DT * v; r[4 * j + 1] = make_float2(x, v);
        v = alpha * v + beta * a.z; x += DT * v; r[4 * j + 2] = make_float2(x, v);
        v = alpha * v + beta * a.w; x += DT * v; r[4 * j + 3] = make_float2(x, v);
    }

    // Two staging rounds: thread-halves -> padded smem -> coalesced global stores.
    float2* out_base = out2 + 1 + blockIdx.x * TILE;
    #pragma unroll
    for (int half = 0; half < 2; half++) {
        __syncthreads();
        if ((tid >> 7) == half) {
            int t = tid & 127;
            #pragma unroll
            for (int k = 0; k < SEG; k++) sout[t * (SEG + 1) + k] = r[k];
        }
        __syncthreads();
        float2* gdst = out_base + half * (TILE / 2);
        #pragma unroll
        for (int w = 0; w < (TILE / 2) / TPB; w++) {    // 16 iterations
            int i2 = tid + TPB * w;
            gdst[i2] = sout[(i2 >> 5) * (SEG + 1) + (i2 & 31)];
        }
    }
}

extern "C" void kernel_launch(void* const* d_in, const int* in_sizes, int n_in,
                              void* d_out, int out_size) {
    const float* init = (const float*)d_in[0];
    const float* act  = (const float*)d_in[1];
    const float* mass = (const float*)d_in[2];
    const float* fric = (const float*)d_in[3];
    float2* out2 = (float2*)d_out;

    const int smem1 = TPB * SSTR * sizeof(float) + TPB * sizeof(float4);       // 40960
    const int smem3 = TPB * SSTR * sizeof(float) + 128 * (SEG + 1) * sizeof(float2); // 70656

    cudaFuncSetAttribute(k_final, cudaFuncAttributeMaxDynamicSharedMemorySize, smem3);

    k_partial<<<NBLK, TPB, smem1>>>(act, mass, fric);
    k_blockscan<<<1, NBLK>>>();
    k_final<<<NBLK, TPB, smem3>>>(act, init, mass, fric, out2);
}